// round 1
// baseline (speedup 1.0000x reference)
#include <cuda_runtime.h>
#include <cuda_bf16.h>

// HartleyCosineConv2d: y[n,c,h,w] = w0*x[h] + a1*(x[h-1]+x[h+1])
//                                 + a2*(x[h-2]+x[h+2]) + a3*(x[h-3]+x[h+3])
// with reflect-101 padding along H. x: (8,256,256,256) fp32, alpha: (256,4).
//
// Strategy: register sliding window along H. One thread owns one float4
// column (4 consecutive w) of one (n,c) slice and walks h=0..H-1.
// Exactly one LDG.128 + one STG.128 per element group -> HBM-compulsory
// traffic only (1.07 GB total).

#define DN 8
#define DC 256
#define DH 256
#define DW 256
#define W4 (DW / 4)   // 64 float4 per row

__global__ __launch_bounds__(256, 4)
void hartley_stencil_kernel(const float4* __restrict__ x,
                            const float*  __restrict__ alpha,
                            float4* __restrict__ y)
{
    // slice = n*C + c; 4 slices per block via threadIdx.y
    const int slice = blockIdx.x * 4 + threadIdx.y;
    const int c     = slice & (DC - 1);
    const int w     = threadIdx.x;           // 0..63, float4 index along W

    const float w0 = __ldg(&alpha[c * 4 + 0]);
    const float a1 = __ldg(&alpha[c * 4 + 1]);
    const float a2 = __ldg(&alpha[c * 4 + 2]);
    const float a3 = __ldg(&alpha[c * 4 + 3]);

    const size_t base = (size_t)slice * (DH * W4) + w;
    const float4* __restrict__ xp = x + base;
    float4*       __restrict__ yp = y + base;

    // Init window for h=0: rows reflect(-3..3) = 3,2,1,0,1,2,3
    float4 r0 = xp[0 * W4];
    float4 r1 = xp[1 * W4];
    float4 r2 = xp[2 * W4];
    float4 r3 = xp[3 * W4];

    float4 win0 = r3, win1 = r2, win2 = r1, win3 = r0,
           win4 = r1, win5 = r2, win6 = r3;

    #pragma unroll 4
    for (int h = 0; h < DH; ++h) {
        float4 out;
        out.x = w0 * win3.x + a1 * (win2.x + win4.x)
                            + a2 * (win1.x + win5.x)
                            + a3 * (win0.x + win6.x);
        out.y = w0 * win3.y + a1 * (win2.y + win4.y)
                            + a2 * (win1.y + win5.y)
                            + a3 * (win0.y + win6.y);
        out.z = w0 * win3.z + a1 * (win2.z + win4.z)
                            + a2 * (win1.z + win5.z)
                            + a3 * (win0.z + win6.z);
        out.w = w0 * win3.w + a1 * (win2.w + win4.w)
                            + a2 * (win1.w + win5.w)
                            + a3 * (win0.w + win6.w);

        yp[(size_t)h * W4] = out;

        // slide window: next center is h+1, need row reflect(h+4)
        win0 = win1; win1 = win2; win2 = win3;
        win3 = win4; win4 = win5; win5 = win6;
        int nh = h + 4;
        if (nh >= DH) nh = 2 * DH - 2 - nh;   // reflect-101 (always in-bounds)
        win6 = xp[(size_t)nh * W4];
    }
}

extern "C" void kernel_launch(void* const* d_in, const int* in_sizes, int n_in,
                              void* d_out, int out_size)
{
    const float4* x     = (const float4*)d_in[0];
    const float*  alpha = (const float*) d_in[1];
    float4*       y     = (float4*)d_out;

    dim3 block(64, 4);                 // 64 float4 columns x 4 slices
    dim3 grid((DN * DC) / 4);          // 512 blocks
    hartley_stencil_kernel<<<grid, block>>>(x, alpha, y);
}